// round 2
// baseline (speedup 1.0000x reference)
#include <cuda_runtime.h>
#include <math.h>

#define NB 128
#define TT 384
#define CC 256
#define HH 4
#define KVH 2
#define DD 64
#define MTOT (NB*TT)   // 49152

// Scratch (static device globals — no allocations)
__device__ float g_Q[NB*HH*TT*DD];    // [B,H,T,D]
__device__ float g_K[NB*KVH*TT*DD];   // [B,KV,T,D]
__device__ float g_V[NB*KVH*TT*DD];   // [B,KV,T,D]
__device__ float g_Y[NB*TT*CC];       // [B*T, C] attention output

// ---------------------------------------------------------------------------
// Kernel 1: QKV projection + RoPE + transpose-scatter
// GEMM: x[49152,256] @ Wcat[256,512] -> (Q 256 | K 128 | V 128) columns
// Block tile 64x64, K-tile 16, 256 threads, 4x4 per thread.
// ---------------------------------------------------------------------------
__global__ __launch_bounds__(256) void qkv_rope_kernel(
    const float* __restrict__ x, const float* __restrict__ Wq,
    const float* __restrict__ Wk, const float* __restrict__ Wv)
{
    __shared__ float As[16][68];   // [k][m], stride 68 keeps float4 alignment
    __shared__ float Bs[16][68];   // [k][n]
    __shared__ float Cs[64][68];   // staged output tile

    const int m0 = blockIdx.x * 64;
    const int n0 = blockIdx.y * 64;   // 0..448; each 64-wide tile = one head

    const float* W; int ldb, noff;
    if (n0 < 256)      { W = Wq; ldb = 256; noff = n0;       }
    else if (n0 < 384) { W = Wk; ldb = 128; noff = n0 - 256; }
    else               { W = Wv; ldb = 128; noff = n0 - 384; }

    const int tid = threadIdx.x;
    const int tx = tid & 15;        // row group
    const int ty = tid >> 4;        // col group

    const int lrow = tid >> 2;          // 0..63, A-tile row to load
    const int lk4  = (tid & 3) << 2;    // 0,4,8,12
    const int bk   = tid >> 6;          // 0..3, B-tile k row
    const int bn   = tid & 63;

    float acc[4][4] = {};

    for (int k0 = 0; k0 < 256; k0 += 16) {
        // A tile (64 x 16), stored transposed As[k][m]
        float4 av = *reinterpret_cast<const float4*>(&x[(m0 + lrow) * 256 + k0 + lk4]);
        As[lk4 + 0][lrow] = av.x;
        As[lk4 + 1][lrow] = av.y;
        As[lk4 + 2][lrow] = av.z;
        As[lk4 + 3][lrow] = av.w;
        // B tile (16 x 64)
        #pragma unroll
        for (int kk = bk; kk < 16; kk += 4)
            Bs[kk][bn] = W[(k0 + kk) * ldb + noff + bn];
        __syncthreads();
        #pragma unroll
        for (int kk = 0; kk < 16; kk++) {
            float4 a = *reinterpret_cast<const float4*>(&As[kk][tx << 2]);
            float4 b = *reinterpret_cast<const float4*>(&Bs[kk][ty << 2]);
            float avv[4] = {a.x, a.y, a.z, a.w};
            float bvv[4] = {b.x, b.y, b.z, b.w};
            #pragma unroll
            for (int i = 0; i < 4; i++)
                #pragma unroll
                for (int j = 0; j < 4; j++)
                    acc[i][j] += avv[i] * bvv[j];
        }
        __syncthreads();
    }

    // Stage raw GEMM result
    #pragma unroll
    for (int i = 0; i < 4; i++)
        #pragma unroll
        for (int j = 0; j < 4; j++)
            Cs[(tx << 2) + i][(ty << 2) + j] = acc[i][j];
    __syncthreads();

    // Cooperative write with RoPE: 4 threads per row, 16 cols each
    const int r   = tid >> 2;
    const int seg = (tid & 3) << 4;
    const int gm  = m0 + r;
    const int b   = gm / TT;
    const int t   = gm - b * TT;

    float* dst;
    bool isV = false;
    if (n0 < 256) {
        int h = n0 >> 6;
        dst = &g_Q[((b * HH + h) * TT + t) * DD];
    } else if (n0 < 384) {
        int h = (n0 - 256) >> 6;
        dst = &g_K[((b * KVH + h) * TT + t) * DD];
    } else {
        int h = (n0 - 384) >> 6;
        dst = &g_V[((b * KVH + h) * TT + t) * DD];
        isV = true;
    }

    if (isV) {
        #pragma unroll
        for (int c = 0; c < 16; c += 4) {
            float4 v = *reinterpret_cast<const float4*>(&Cs[r][seg + c]);
            *reinterpret_cast<float4*>(&dst[seg + c]) = v;
        }
    } else {
        const float tf = (float)t;
        #pragma unroll
        for (int c = 0; c < 16; c++) {
            int d  = seg + c;
            int d0 = d & 31;
            // inv_freq = 10000^(-d0/32) computed via accurate exp2f
            float invf = exp2f(-13.287712379549449f * ((float)d0 * (1.0f / 32.0f)));
            float ang = tf * invf;
            float cs = cosf(ang), sn = sinf(ang);
            float val;
            if (d < 32) val = Cs[r][d] * cs - Cs[r][d + 32] * sn;
            else        val = Cs[r][d] * cs + Cs[r][d - 32] * sn;
            dst[d] = val;
        }
    }
}

// ---------------------------------------------------------------------------
// Kernel 2: causal flash attention (GQA). One thread per query row.
// Block: 64 query rows, iterate 32-key tiles; q/o in registers, K/V in smem.
// ---------------------------------------------------------------------------
__global__ __launch_bounds__(64) void attn_kernel()
{
    __shared__ float ks[32 * 64];
    __shared__ float vs[32 * 64];

    const int qt = blockIdx.x;    // 0..5
    const int h  = blockIdx.y;    // 0..3
    const int b  = blockIdx.z;    // 0..127
    const int kv = h >> 1;        // REP = 2
    const int r  = threadIdx.x;   // 0..63
    const int qi = qt * 64 + r;

    const float* Qp = &g_Q[((b * HH + h) * TT + qi) * DD];
    float q[64];
    #pragma unroll
    for (int d = 0; d < 64; d += 4) {
        float4 v = *reinterpret_cast<const float4*>(&Qp[d]);
        q[d] = v.x; q[d + 1] = v.y; q[d + 2] = v.z; q[d + 3] = v.w;
    }
    float o[64];
    #pragma unroll
    for (int d = 0; d < 64; d++) o[d] = 0.f;
    float m = -1e30f, l = 0.f;

    const float* Kbase = &g_K[((b * KVH + kv) * TT) * DD];
    const float* Vbase = &g_V[((b * KVH + kv) * TT) * DD];

    const int nkt = 2 * qt + 2;   // causal: key tiles 0 .. qt*64+63
    for (int kt = 0; kt < nkt; kt++) {
        const float4* ksrc = reinterpret_cast<const float4*>(Kbase + kt * 32 * 64);
        const float4* vsrc = reinterpret_cast<const float4*>(Vbase + kt * 32 * 64);
        float4* kdst = reinterpret_cast<float4*>(ks);
        float4* vdst = reinterpret_cast<float4*>(vs);
        #pragma unroll
        for (int i = threadIdx.x; i < 512; i += 64) {
            kdst[i] = ksrc[i];
            vdst[i] = vsrc[i];
        }
        __syncthreads();

        float s[32];
        #pragma unroll
        for (int j = 0; j < 32; j++) {
            float acc = 0.f;
            #pragma unroll
            for (int d = 0; d < 64; d++)
                acc += q[d] * ks[j * 64 + d];
            int kj = kt * 32 + j;
            s[j] = (kj <= qi) ? acc * 0.125f : -1e30f;
        }

        float mt = m;
        #pragma unroll
        for (int j = 0; j < 32; j++) mt = fmaxf(mt, s[j]);
        float corr = __expf(m - mt);
        l *= corr;
        #pragma unroll
        for (int d = 0; d < 64; d++) o[d] *= corr;

        #pragma unroll
        for (int j = 0; j < 32; j++) {
            float p = __expf(s[j] - mt);
            l += p;
            #pragma unroll
            for (int d = 0; d < 64; d++)
                o[d] += p * vs[j * 64 + d];
        }
        m = mt;
        __syncthreads();
    }

    float inv = 1.f / l;
    float* Yp = &g_Y[(b * TT + qi) * CC + h * DD];
    #pragma unroll
    for (int d = 0; d < 64; d += 4) {
        float4 v;
        v.x = o[d] * inv; v.y = o[d + 1] * inv;
        v.z = o[d + 2] * inv; v.w = o[d + 3] * inv;
        *reinterpret_cast<float4*>(&Yp[d]) = v;
    }
}

// ---------------------------------------------------------------------------
// Kernel 3: output projection Y[49152,256] @ Wo[256,256] -> out
// ---------------------------------------------------------------------------
__global__ __launch_bounds__(256) void proj_kernel(
    const float* __restrict__ Wo, float* __restrict__ out)
{
    __shared__ float As[16][68];
    __shared__ float Bs[16][68];
    __shared__ float Cs[64][68];

    const int m0 = blockIdx.x * 64;
    const int n0 = blockIdx.y * 64;

    const int tid = threadIdx.x;
    const int tx = tid & 15;
    const int ty = tid >> 4;

    const int lrow = tid >> 2;
    const int lk4  = (tid & 3) << 2;
    const int bk   = tid >> 6;
    const int bn   = tid & 63;

    float acc[4][4] = {};

    for (int k0 = 0; k0 < 256; k0 += 16) {
        float4 av = *reinterpret_cast<const float4*>(&g_Y[(m0 + lrow) * 256 + k0 + lk4]);
        As[lk4 + 0][lrow] = av.x;
        As[lk4 + 1][lrow] = av.y;
        As[lk4 + 2][lrow] = av.z;
        As[lk4 + 3][lrow] = av.w;
        #pragma unroll
        for (int kk = bk; kk < 16; kk += 4)
            Bs[kk][bn] = Wo[(k0 + kk) * 256 + n0 + bn];
        __syncthreads();
        #pragma unroll
        for (int kk = 0; kk < 16; kk++) {
            float4 a = *reinterpret_cast<const float4*>(&As[kk][tx << 2]);
            float4 b = *reinterpret_cast<const float4*>(&Bs[kk][ty << 2]);
            float avv[4] = {a.x, a.y, a.z, a.w};
            float bvv[4] = {b.x, b.y, b.z, b.w};
            #pragma unroll
            for (int i = 0; i < 4; i++)
                #pragma unroll
                for (int j = 0; j < 4; j++)
                    acc[i][j] += avv[i] * bvv[j];
        }
        __syncthreads();
    }

    #pragma unroll
    for (int i = 0; i < 4; i++)
        #pragma unroll
        for (int j = 0; j < 4; j++)
            Cs[(tx << 2) + i][(ty << 2) + j] = acc[i][j];
    __syncthreads();

    const int r   = tid >> 2;
    const int seg = (tid & 3) << 4;
    float* dst = &out[(m0 + r) * 256 + n0];
    #pragma unroll
    for (int c = 0; c < 16; c += 4) {
        float4 v = *reinterpret_cast<const float4*>(&Cs[r][seg + c]);
        *reinterpret_cast<float4*>(&dst[seg + c]) = v;
    }
}

// ---------------------------------------------------------------------------
extern "C" void kernel_launch(void* const* d_in, const int* in_sizes, int n_in,
                              void* d_out, int out_size)
{
    const float* x  = (const float*)d_in[0];
    const float* Wq = (const float*)d_in[1];
    const float* Wk = (const float*)d_in[2];
    const float* Wv = (const float*)d_in[3];
    const float* Wo = (const float*)d_in[4];
    float* out = (float*)d_out;

    dim3 g1(MTOT / 64, 8);
    qkv_rope_kernel<<<g1, 256>>>(x, Wq, Wk, Wv);

    dim3 g2(TT / 64, HH, NB);
    attn_kernel<<<g2, 64>>>();

    dim3 g3(MTOT / 64, CC / 64);
    proj_kernel<<<g3, 256>>>(Wo, out);
}

// round 4
// speedup vs baseline: 1.6638x; 1.6638x over previous
#include <cuda_runtime.h>
#include <math.h>
#include <stdint.h>

#define NB 128
#define TT 384
#define CC 256
#define HH 4
#define KVH 2
#define DD 64
#define MTOT (NB*TT)   // 49152

// Scratch (static device globals — no allocations)
__device__ float g_Q[NB*HH*TT*DD];    // [B,H,T,D]
__device__ float g_K[NB*KVH*TT*DD];   // [B,KV,T,D]
__device__ float g_V[NB*KVH*TT*DD];   // [B,KV,T,D]
__device__ float g_Y[NB*TT*CC];       // [B*T, C] attention output

// ---------------------------------------------------------------------------
// tf32 helpers
// ---------------------------------------------------------------------------
__device__ __forceinline__ uint32_t f2tf32(float x) {
    uint32_t u;
    asm("cvt.rna.tf32.f32 %0, %1;" : "=r"(u) : "f"(x));
    return u;
}

__device__ __forceinline__ void mma_tf32(float* d, const uint32_t* a, const uint32_t* b) {
    asm volatile(
        "mma.sync.aligned.m16n8k8.row.col.f32.tf32.tf32.f32 "
        "{%0,%1,%2,%3}, {%4,%5,%6,%7}, {%8,%9}, {%0,%1,%2,%3};"
        : "+f"(d[0]), "+f"(d[1]), "+f"(d[2]), "+f"(d[3])
        : "r"(a[0]), "r"(a[1]), "r"(a[2]), "r"(a[3]),
          "r"(b[0]), "r"(b[1]));
}

// ---------------------------------------------------------------------------
// tf32 GEMM, block tile 128x128, K=256 in steps of 16.
// 8 warps, each warp 64(M)x32(N) = 4x4 grid of m16n8k8 mmas.
// MODE 0: qkv projection (A = x, B = Wq|Wk|Wv concat cols) + RoPE epilogue
// MODE 1: output projection (A = g_Y read via device symbol, B = Wo) -> out
// Dynamic smem: As[16][136] u32 + Bs[16][136] u32 + Cs[64][132] float = 51200 B
// ---------------------------------------------------------------------------
template<int MODE>
__global__ __launch_bounds__(256) void gemm_tf32_kernel(
    const float* __restrict__ Ain,
    const float* __restrict__ W0, const float* __restrict__ W1,
    const float* __restrict__ W2,
    float* __restrict__ out)
{
    extern __shared__ char smraw[];
    uint32_t* As = (uint32_t*)smraw;            // [16][136]
    uint32_t* Bs = As + 16 * 136;               // [16][136]
    float*    Cs = (float*)(Bs + 16 * 136);     // [64][132]

    // MODE 1 reads the attention output from the device-global scratch.
    // (Passing g_Y as a host-side kernel argument is invalid — the host only
    //  sees a shadow symbol. This was the R3 bug.)
    const float* A = (MODE == 1) ? (const float*)g_Y : Ain;

    const int m0 = blockIdx.x * 128;
    const int n0 = blockIdx.y * 128;

    const float* W; int ldb, noff;
    if (MODE == 1)     { W = W0; ldb = CC;  noff = n0;       }
    else if (n0 < 256) { W = W0; ldb = 256; noff = n0;       }
    else if (n0 < 384) { W = W1; ldb = 128; noff = n0 - 256; }
    else               { W = W2; ldb = 128; noff = n0 - 384; }

    const int tid  = threadIdx.x;
    const int lane = tid & 31;
    const int wid  = tid >> 5;
    const int wm   = wid >> 2;   // 0..1 -> rows wm*64
    const int wn   = wid & 3;    // 0..3 -> cols wn*32
    const int grp  = lane >> 2;  // 0..7
    const int tg   = lane & 3;   // 0..3

    float acc[4][4][4];
    #pragma unroll
    for (int i = 0; i < 4; i++)
        #pragma unroll
        for (int j = 0; j < 4; j++)
            #pragma unroll
            for (int r = 0; r < 4; r++) acc[i][j][r] = 0.f;

    for (int k0 = 0; k0 < CC; k0 += 16) {
        // --- fill smem (convert to tf32 once here) ---
        #pragma unroll
        for (int u = 0; u < 2; u++) {
            int f = tid + u * 256;
            // A tile: 128 rows x 16 k, stored transposed As[k][m], stride 136
            int arow = f >> 2, ak4 = (f & 3) << 2;
            float4 av = *reinterpret_cast<const float4*>(&A[(m0 + arow) * CC + k0 + ak4]);
            As[(ak4 + 0) * 136 + arow] = f2tf32(av.x);
            As[(ak4 + 1) * 136 + arow] = f2tf32(av.y);
            As[(ak4 + 2) * 136 + arow] = f2tf32(av.z);
            As[(ak4 + 3) * 136 + arow] = f2tf32(av.w);
            // B tile: 16 k x 128 n, stored Bs[k][n], stride 136
            int bk = f >> 5, bn = (f & 31) << 2;
            float4 bv = *reinterpret_cast<const float4*>(&W[(k0 + bk) * ldb + noff + bn]);
            uint4 bu;
            bu.x = f2tf32(bv.x); bu.y = f2tf32(bv.y);
            bu.z = f2tf32(bv.z); bu.w = f2tf32(bv.w);
            *reinterpret_cast<uint4*>(&Bs[bk * 136 + bn]) = bu;
        }
        __syncthreads();

        #pragma unroll
        for (int kk = 0; kk < 16; kk += 8) {
            uint32_t af[4][4];
            #pragma unroll
            for (int i = 0; i < 4; i++) {
                int mb = wm * 64 + i * 16 + grp;
                af[i][0] = As[(kk + tg    ) * 136 + mb    ];
                af[i][1] = As[(kk + tg    ) * 136 + mb + 8];
                af[i][2] = As[(kk + tg + 4) * 136 + mb    ];
                af[i][3] = As[(kk + tg + 4) * 136 + mb + 8];
            }
            uint32_t bf[4][2];
            #pragma unroll
            for (int j = 0; j < 4; j++) {
                int nb = wn * 32 + j * 8 + grp;
                bf[j][0] = Bs[(kk + tg    ) * 136 + nb];
                bf[j][1] = Bs[(kk + tg + 4) * 136 + nb];
            }
            #pragma unroll
            for (int i = 0; i < 4; i++)
                #pragma unroll
                for (int j = 0; j < 4; j++)
                    mma_tf32(acc[i][j], af[i], bf[j]);
        }
        __syncthreads();
    }

    // --- epilogue: two 64-row halves staged through Cs ---
    #pragma unroll
    for (int half = 0; half < 2; half++) {
        if (wm == half) {
            #pragma unroll
            for (int i = 0; i < 4; i++)
                #pragma unroll
                for (int j = 0; j < 4; j++)
                    #pragma unroll
                    for (int rr = 0; rr < 4; rr++) {
                        int row = i * 16 + grp + ((rr >> 1) << 3);
                        int col = wn * 32 + j * 8 + tg * 2 + (rr & 1);
                        Cs[row * 132 + col] = acc[i][j][rr];
                    }
        }
        __syncthreads();

        const int r   = tid >> 2;          // 0..63
        const int seg = (tid & 3) << 5;    // 0,32,64,96
        const int gm  = m0 + half * 64 + r;
        const float* Crow = &Cs[r * 132];

        if (MODE == 1) {
            float* dst = &out[gm * CC + n0 + seg];
            #pragma unroll
            for (int c = 0; c < 32; c += 4)
                *reinterpret_cast<float4*>(&dst[c]) =
                    *reinterpret_cast<const float4*>(&Crow[seg + c]);
        } else {
            const int bb = gm / TT;
            const int t  = gm - bb * TT;
            const int cglob = n0 + seg;
            if (cglob >= 384) {
                // V: straight copy
                int hh = (cglob - 384) >> 6;
                float* dst = &g_V[((bb * KVH + hh) * TT + t) * DD + (cglob & 63)];
                #pragma unroll
                for (int c = 0; c < 32; c += 4)
                    *reinterpret_cast<float4*>(&dst[c]) =
                        *reinterpret_cast<const float4*>(&Crow[seg + c]);
            } else {
                float* dst;
                if (cglob < 256) dst = &g_Q[((bb * HH  + (cglob >> 6)       ) * TT + t) * DD];
                else             dst = &g_K[((bb * KVH + ((cglob - 256) >> 6)) * TT + t) * DD];
                const int dhalf = cglob & 32;   // 0: first rope half, 32: second
                const float tf = (float)t;
                #pragma unroll
                for (int c = 0; c < 32; c += 4) {
                    float4 v;
                    float* vp = &v.x;
                    #pragma unroll
                    for (int e = 0; e < 4; e++) {
                        int cc = c + e;
                        float invf = exp2f(-0.41524101186f * (float)cc);
                        float ang = tf * invf;
                        float sn, cs;
                        sincosf(ang, &sn, &cs);
                        float val;
                        if (dhalf == 0)
                            val = Crow[seg + cc] * cs - Crow[seg + 32 + cc] * sn;
                        else
                            val = Crow[seg + cc] * cs + Crow[seg - 32 + cc] * sn;
                        vp[e] = val;
                    }
                    *reinterpret_cast<float4*>(&dst[dhalf + c]) = v;
                }
            }
        }
        __syncthreads();
    }
}

// ---------------------------------------------------------------------------
// Kernel 2: causal flash attention (GQA). One thread per query row,
// 128 threads/block, float4 smem reads, scores staged in per-thread smem col.
// ---------------------------------------------------------------------------
__global__ __launch_bounds__(128) void attn_kernel()
{
    __shared__ float ks[32 * 64];
    __shared__ float vs[32 * 64];
    __shared__ float ssm[32 * 132];   // [j][r], stride 132

    const int qt = blockIdx.x;    // 0..2
    const int h  = blockIdx.y;    // 0..3
    const int b  = blockIdx.z;    // 0..127
    const int kv = h >> 1;
    const int r  = threadIdx.x;   // 0..127
    const int qi = qt * 128 + r;

    const float* Qp = &g_Q[((b * HH + h) * TT + qi) * DD];
    float q[64];
    #pragma unroll
    for (int d = 0; d < 64; d += 4) {
        float4 v = *reinterpret_cast<const float4*>(&Qp[d]);
        q[d] = v.x; q[d + 1] = v.y; q[d + 2] = v.z; q[d + 3] = v.w;
    }
    float o[64];
    #pragma unroll
    for (int d = 0; d < 64; d++) o[d] = 0.f;
    float m = -1e30f, l = 0.f;

    const float* Kbase = &g_K[((b * KVH + kv) * TT) * DD];
    const float* Vbase = &g_V[((b * KVH + kv) * TT) * DD];

    const int nkt = 4 * qt + 4;
    for (int kt = 0; kt < nkt; kt++) {
        const float4* ksrc = reinterpret_cast<const float4*>(Kbase + kt * 2048);
        const float4* vsrc = reinterpret_cast<const float4*>(Vbase + kt * 2048);
        float4* kdst = reinterpret_cast<float4*>(ks);
        float4* vdst = reinterpret_cast<float4*>(vs);
        #pragma unroll
        for (int i = r; i < 512; i += 128) {
            kdst[i] = ksrc[i];
            vdst[i] = vsrc[i];
        }
        __syncthreads();

        // scores -> private smem column
        #pragma unroll 2
        for (int j = 0; j < 32; j++) {
            const float4* kk4 = reinterpret_cast<const float4*>(&ks[j * 64]);
            float acc = 0.f;
            #pragma unroll
            for (int d = 0; d < 16; d++) {
                float4 kv4 = kk4[d];
                acc += q[4*d] * kv4.x + q[4*d+1] * kv4.y
                     + q[4*d+2] * kv4.z + q[4*d+3] * kv4.w;
            }
            int kj = kt * 32 + j;
            ssm[j * 132 + r] = (kj <= qi) ? acc * 0.125f : -1e30f;
        }
        // (ssm column is thread-private: no sync needed)

        float mt = m;
        #pragma unroll
        for (int j = 0; j < 32; j++) mt = fmaxf(mt, ssm[j * 132 + r]);
        float corr = __expf(m - mt);
        l *= corr;
        #pragma unroll
        for (int d = 0; d < 64; d++) o[d] *= corr;

        #pragma unroll 2
        for (int j = 0; j < 32; j++) {
            float p = __expf(ssm[j * 132 + r] - mt);
            l += p;
            const float4* vv4 = reinterpret_cast<const float4*>(&vs[j * 64]);
            #pragma unroll
            for (int d = 0; d < 16; d++) {
                float4 v4 = vv4[d];
                o[4*d]   += p * v4.x; o[4*d+1] += p * v4.y;
                o[4*d+2] += p * v4.z; o[4*d+3] += p * v4.w;
            }
        }
        m = mt;
        __syncthreads();
    }

    float inv = 1.f / l;
    float* Yp = &g_Y[(b * TT + qi) * CC + h * DD];
    #pragma unroll
    for (int d = 0; d < 64; d += 4) {
        float4 v;
        v.x = o[d] * inv;     v.y = o[d + 1] * inv;
        v.z = o[d + 2] * inv; v.w = o[d + 3] * inv;
        *reinterpret_cast<float4*>(&Yp[d]) = v;
    }
}

// ---------------------------------------------------------------------------
extern "C" void kernel_launch(void* const* d_in, const int* in_sizes, int n_in,
                              void* d_out, int out_size)
{
    const float* x  = (const float*)d_in[0];
    const float* Wq = (const float*)d_in[1];
    const float* Wk = (const float*)d_in[2];
    const float* Wv = (const float*)d_in[3];
    const float* Wo = (const float*)d_in[4];
    float* out = (float*)d_out;

    const int smem = 51200;
    static bool attr_done = false;
    if (!attr_done) {
        cudaFuncSetAttribute(gemm_tf32_kernel<0>,
                             cudaFuncAttributeMaxDynamicSharedMemorySize, smem);
        cudaFuncSetAttribute(gemm_tf32_kernel<1>,
                             cudaFuncAttributeMaxDynamicSharedMemorySize, smem);
        attr_done = true;
    }

    dim3 g1(MTOT / 128, 512 / 128);
    gemm_tf32_kernel<0><<<g1, 256, smem>>>(x, Wq, Wk, Wv, nullptr);

    dim3 g2(TT / 128, HH, NB);
    attn_kernel<<<g2, 128>>>();

    dim3 g3(MTOT / 128, CC / 128);
    gemm_tf32_kernel<1><<<g3, 256, smem>>>(nullptr, Wo, nullptr, nullptr, out);
}

// round 5
// speedup vs baseline: 3.2555x; 1.9567x over previous
#include <cuda_runtime.h>
#include <math.h>
#include <stdint.h>

#define NB 128
#define TT 384
#define CC 256
#define HH 4
#define KVH 2
#define DD 64
#define MTOT (NB*TT)   // 49152

// Scratch (static device globals — no allocations)
__device__ float g_Q[NB*HH*TT*DD];    // [B,H,T,D]
__device__ float g_K[NB*KVH*TT*DD];   // [B,KV,T,D]
__device__ float g_V[NB*KVH*TT*DD];   // [B,KV,T,D]
__device__ float g_Y[NB*TT*CC];       // [B*T, C] attention output

// ---------------------------------------------------------------------------
// tf32 helpers
// ---------------------------------------------------------------------------
__device__ __forceinline__ uint32_t f2tf32(float x) {
    uint32_t u;
    asm("cvt.rna.tf32.f32 %0, %1;" : "=r"(u) : "f"(x));
    return u;
}

__device__ __forceinline__ void mma_tf32(float* d, const uint32_t* a, const uint32_t* b) {
    asm volatile(
        "mma.sync.aligned.m16n8k8.row.col.f32.tf32.tf32.f32 "
        "{%0,%1,%2,%3}, {%4,%5,%6,%7}, {%8,%9}, {%0,%1,%2,%3};"
        : "+f"(d[0]), "+f"(d[1]), "+f"(d[2]), "+f"(d[3])
        : "r"(a[0]), "r"(a[1]), "r"(a[2]), "r"(a[3]),
          "r"(b[0]), "r"(b[1]));
}

// ---------------------------------------------------------------------------
// tf32 GEMM, block tile 128x128, K=256 in steps of 16. (unchanged from R4)
// ---------------------------------------------------------------------------
template<int MODE>
__global__ __launch_bounds__(256) void gemm_tf32_kernel(
    const float* __restrict__ Ain,
    const float* __restrict__ W0, const float* __restrict__ W1,
    const float* __restrict__ W2,
    float* __restrict__ out)
{
    extern __shared__ char smraw[];
    uint32_t* As = (uint32_t*)smraw;            // [16][136]
    uint32_t* Bs = As + 16 * 136;               // [16][136]
    float*    Cs = (float*)(Bs + 16 * 136);     // [64][132]

    const float* A = (MODE == 1) ? (const float*)g_Y : Ain;

    const int m0 = blockIdx.x * 128;
    const int n0 = blockIdx.y * 128;

    const float* W; int ldb, noff;
    if (MODE == 1)     { W = W0; ldb = CC;  noff = n0;       }
    else if (n0 < 256) { W = W0; ldb = 256; noff = n0;       }
    else if (n0 < 384) { W = W1; ldb = 128; noff = n0 - 256; }
    else               { W = W2; ldb = 128; noff = n0 - 384; }

    const int tid  = threadIdx.x;
    const int lane = tid & 31;
    const int wid  = tid >> 5;
    const int wm   = wid >> 2;
    const int wn   = wid & 3;
    const int grp  = lane >> 2;
    const int tg   = lane & 3;

    float acc[4][4][4];
    #pragma unroll
    for (int i = 0; i < 4; i++)
        #pragma unroll
        for (int j = 0; j < 4; j++)
            #pragma unroll
            for (int r = 0; r < 4; r++) acc[i][j][r] = 0.f;

    for (int k0 = 0; k0 < CC; k0 += 16) {
        #pragma unroll
        for (int u = 0; u < 2; u++) {
            int f = tid + u * 256;
            int arow = f >> 2, ak4 = (f & 3) << 2;
            float4 av = *reinterpret_cast<const float4*>(&A[(m0 + arow) * CC + k0 + ak4]);
            As[(ak4 + 0) * 136 + arow] = f2tf32(av.x);
            As[(ak4 + 1) * 136 + arow] = f2tf32(av.y);
            As[(ak4 + 2) * 136 + arow] = f2tf32(av.z);
            As[(ak4 + 3) * 136 + arow] = f2tf32(av.w);
            int bk = f >> 5, bn = (f & 31) << 2;
            float4 bv = *reinterpret_cast<const float4*>(&W[(k0 + bk) * ldb + noff + bn]);
            uint4 bu;
            bu.x = f2tf32(bv.x); bu.y = f2tf32(bv.y);
            bu.z = f2tf32(bv.z); bu.w = f2tf32(bv.w);
            *reinterpret_cast<uint4*>(&Bs[bk * 136 + bn]) = bu;
        }
        __syncthreads();

        #pragma unroll
        for (int kk = 0; kk < 16; kk += 8) {
            uint32_t af[4][4];
            #pragma unroll
            for (int i = 0; i < 4; i++) {
                int mb = wm * 64 + i * 16 + grp;
                af[i][0] = As[(kk + tg    ) * 136 + mb    ];
                af[i][1] = As[(kk + tg    ) * 136 + mb + 8];
                af[i][2] = As[(kk + tg + 4) * 136 + mb    ];
                af[i][3] = As[(kk + tg + 4) * 136 + mb + 8];
            }
            uint32_t bf[4][2];
            #pragma unroll
            for (int j = 0; j < 4; j++) {
                int nb = wn * 32 + j * 8 + grp;
                bf[j][0] = Bs[(kk + tg    ) * 136 + nb];
                bf[j][1] = Bs[(kk + tg + 4) * 136 + nb];
            }
            #pragma unroll
            for (int i = 0; i < 4; i++)
                #pragma unroll
                for (int j = 0; j < 4; j++)
                    mma_tf32(acc[i][j], af[i], bf[j]);
        }
        __syncthreads();
    }

    #pragma unroll
    for (int half = 0; half < 2; half++) {
        if (wm == half) {
            #pragma unroll
            for (int i = 0; i < 4; i++)
                #pragma unroll
                for (int j = 0; j < 4; j++)
                    #pragma unroll
                    for (int rr = 0; rr < 4; rr++) {
                        int row = i * 16 + grp + ((rr >> 1) << 3);
                        int col = wn * 32 + j * 8 + tg * 2 + (rr & 1);
                        Cs[row * 132 + col] = acc[i][j][rr];
                    }
        }
        __syncthreads();

        const int r   = tid >> 2;
        const int seg = (tid & 3) << 5;
        const int gm  = m0 + half * 64 + r;
        const float* Crow = &Cs[r * 132];

        if (MODE == 1) {
            float* dst = &out[gm * CC + n0 + seg];
            #pragma unroll
            for (int c = 0; c < 32; c += 4)
                *reinterpret_cast<float4*>(&dst[c]) =
                    *reinterpret_cast<const float4*>(&Crow[seg + c]);
        } else {
            const int bb = gm / TT;
            const int t  = gm - bb * TT;
            const int cglob = n0 + seg;
            if (cglob >= 384) {
                int hh = (cglob - 384) >> 6;
                float* dst = &g_V[((bb * KVH + hh) * TT + t) * DD + (cglob & 63)];
                #pragma unroll
                for (int c = 0; c < 32; c += 4)
                    *reinterpret_cast<float4*>(&dst[c]) =
                        *reinterpret_cast<const float4*>(&Crow[seg + c]);
            } else {
                float* dst;
                if (cglob < 256) dst = &g_Q[((bb * HH  + (cglob >> 6)       ) * TT + t) * DD];
                else             dst = &g_K[((bb * KVH + ((cglob - 256) >> 6)) * TT + t) * DD];
                const int dhalf = cglob & 32;
                const float tf = (float)t;
                #pragma unroll
                for (int c = 0; c < 32; c += 4) {
                    float4 v;
                    float* vp = &v.x;
                    #pragma unroll
                    for (int e = 0; e < 4; e++) {
                        int cc = c + e;
                        float invf = exp2f(-0.41524101186f * (float)cc);
                        float ang = tf * invf;
                        float sn, cs;
                        sincosf(ang, &sn, &cs);
                        float val;
                        if (dhalf == 0)
                            val = Crow[seg + cc] * cs - Crow[seg + 32 + cc] * sn;
                        else
                            val = Crow[seg + cc] * cs + Crow[seg - 32 + cc] * sn;
                        vp[e] = val;
                    }
                    *reinterpret_cast<float4*>(&dst[dhalf + c]) = v;
                }
            }
        }
        __syncthreads();
    }
}

// ---------------------------------------------------------------------------
// Kernel 2: causal flash attention with tf32 mma.
// Block: 64 q-rows × one head. 4 warps (128 threads).
// S = Q K^T  : warp w owns q-rows w*16..w*16+15 (standard m16n8k8 layout)
// PV as O^T  : O^T = V^T @ P^T — warp w owns d-rows w*16..w*16+15,
//              V stays in natural [key][d] layout (no transpose in smem),
//              P broadcast through smem, corr/l broadcast via small arrays.
// ---------------------------------------------------------------------------
__global__ __launch_bounds__(128) void attn_mma_kernel()
{
    extern __shared__ uint32_t sm[];
    uint32_t* Qs = sm;                 // [64][68] tf32, row-major [qrow][d]
    uint32_t* Ks = Qs + 64 * 68;       // [64][68] tf32, [key][d]
    uint32_t* Vs = Ks + 64 * 68;       // [64][68] tf32, [key][d]
    uint32_t* Ps = Vs + 64 * 68;       // [64][68] tf32, [qrow][key]
    float* sm_corr = (float*)(Ps + 64 * 68);  // [64]
    float* sm_l    = sm_corr + 64;             // [64]

    const int qt = gridDim.x - 1 - blockIdx.x;  // heavy tiles first
    const int h  = blockIdx.y;
    const int b  = blockIdx.z;
    const int kv = h >> 1;
    const int tid  = threadIdx.x;
    const int lane = tid & 31;
    const int wid  = tid >> 5;
    const int grp  = lane >> 2;
    const int tg   = lane & 3;
    const int wrow = wid * 16;   // q-row base (S) / d-row base (O^T)

    // Load Q tile (rows qt*64..+63)
    const float* Qg = &g_Q[((b * HH + h) * TT + qt * 64) * DD];
    #pragma unroll
    for (int i = tid; i < 64 * 16; i += 128) {
        int r = i >> 4, c4 = (i & 15) << 2;
        float4 v = *reinterpret_cast<const float4*>(&Qg[r * 64 + c4]);
        uint4 u;
        u.x = f2tf32(v.x); u.y = f2tf32(v.y);
        u.z = f2tf32(v.z); u.w = f2tf32(v.w);
        *reinterpret_cast<uint4*>(&Qs[r * 68 + c4]) = u;
    }

    float m0 = -1e30f, m1 = -1e30f;   // softmax state for q-rows wrow+grp, +8
    float l0 = 0.f,   l1 = 0.f;
    float acc_o[8][4];                 // O^T: d-rows wrow+grp/+8, q-cols j*8+2tg..
    #pragma unroll
    for (int j = 0; j < 8; j++)
        #pragma unroll
        for (int e = 0; e < 4; e++) acc_o[j][e] = 0.f;

    const float* Kg = &g_K[((b * KVH + kv) * TT) * DD];
    const float* Vg = &g_V[((b * KVH + kv) * TT) * DD];

    for (int kt = 0; kt <= qt; kt++) {
        __syncthreads();   // protect Ks/Vs/Ps from previous iteration readers
        #pragma unroll
        for (int i = tid; i < 64 * 16; i += 128) {
            int r = i >> 4, c4 = (i & 15) << 2;
            float4 v = *reinterpret_cast<const float4*>(&Kg[(kt * 64 + r) * 64 + c4]);
            uint4 u;
            u.x = f2tf32(v.x); u.y = f2tf32(v.y);
            u.z = f2tf32(v.z); u.w = f2tf32(v.w);
            *reinterpret_cast<uint4*>(&Ks[r * 68 + c4]) = u;
            float4 w = *reinterpret_cast<const float4*>(&Vg[(kt * 64 + r) * 64 + c4]);
            uint4 uw;
            uw.x = f2tf32(w.x); uw.y = f2tf32(w.y);
            uw.z = f2tf32(w.z); uw.w = f2tf32(w.w);
            *reinterpret_cast<uint4*>(&Vs[r * 68 + c4]) = uw;
        }
        __syncthreads();

        // ---- S = Q K^T : warp owns q-rows wrow..wrow+15, all 64 keys ----
        float s[8][4];
        #pragma unroll
        for (int j = 0; j < 8; j++)
            #pragma unroll
            for (int e = 0; e < 4; e++) s[j][e] = 0.f;

        #pragma unroll
        for (int kk = 0; kk < 64; kk += 8) {
            uint32_t a[4];
            a[0] = Qs[(wrow + grp    ) * 68 + kk + tg    ];
            a[1] = Qs[(wrow + grp + 8) * 68 + kk + tg    ];
            a[2] = Qs[(wrow + grp    ) * 68 + kk + tg + 4];
            a[3] = Qs[(wrow + grp + 8) * 68 + kk + tg + 4];
            #pragma unroll
            for (int j = 0; j < 8; j++) {
                uint32_t bf[2];
                bf[0] = Ks[(j * 8 + grp) * 68 + kk + tg    ];
                bf[1] = Ks[(j * 8 + grp) * 68 + kk + tg + 4];
                mma_tf32(s[j], a, bf);
            }
        }

        // ---- scale, causal mask, online softmax ----
        const int row0 = qt * 64 + wrow + grp;
        const int row1 = row0 + 8;
        float mx0 = -1e30f, mx1 = -1e30f;
        #pragma unroll
        for (int j = 0; j < 8; j++) {
            #pragma unroll
            for (int e = 0; e < 4; e++) {
                float v = s[j][e] * 0.125f;
                if (kt == qt) {
                    int col = kt * 64 + j * 8 + 2 * tg + (e & 1);
                    int row = (e < 2) ? row0 : row1;
                    if (col > row) v = -1e30f;
                }
                s[j][e] = v;
            }
            mx0 = fmaxf(mx0, fmaxf(s[j][0], s[j][1]));
            mx1 = fmaxf(mx1, fmaxf(s[j][2], s[j][3]));
        }
        mx0 = fmaxf(mx0, __shfl_xor_sync(0xffffffffu, mx0, 1));
        mx0 = fmaxf(mx0, __shfl_xor_sync(0xffffffffu, mx0, 2));
        mx1 = fmaxf(mx1, __shfl_xor_sync(0xffffffffu, mx1, 1));
        mx1 = fmaxf(mx1, __shfl_xor_sync(0xffffffffu, mx1, 2));

        float mn0 = fmaxf(m0, mx0), mn1 = fmaxf(m1, mx1);
        float c0 = __expf(m0 - mn0), c1 = __expf(m1 - mn1);
        m0 = mn0; m1 = mn1;
        l0 *= c0; l1 *= c1;

        // P -> smem (tf32); l accumulates the *rounded* weights for consistency
        #pragma unroll
        for (int j = 0; j < 8; j++) {
            uint32_t p0 = f2tf32(__expf(s[j][0] - mn0));
            uint32_t p1 = f2tf32(__expf(s[j][1] - mn0));
            uint32_t p2 = f2tf32(__expf(s[j][2] - mn1));
            uint32_t p3 = f2tf32(__expf(s[j][3] - mn1));
            l0 += __uint_as_float(p0) + __uint_as_float(p1);
            l1 += __uint_as_float(p2) + __uint_as_float(p3);
            Ps[(wrow + grp    ) * 68 + j * 8 + 2 * tg    ] = p0;
            Ps[(wrow + grp    ) * 68 + j * 8 + 2 * tg + 1] = p1;
            Ps[(wrow + grp + 8) * 68 + j * 8 + 2 * tg    ] = p2;
            Ps[(wrow + grp + 8) * 68 + j * 8 + 2 * tg + 1] = p3;
        }
        // broadcast per-row corr to all warps
        if (tg == 0) {
            sm_corr[wrow + grp    ] = c0;
            sm_corr[wrow + grp + 8] = c1;
        }
        __syncthreads();

        // ---- O^T += V^T @ P^T : warp owns d-rows wrow..wrow+15, all 64 q ----
        // scale accumulators by per-q-column corr
        #pragma unroll
        for (int j = 0; j < 8; j++) {
            float cc0 = sm_corr[j * 8 + 2 * tg    ];
            float cc1 = sm_corr[j * 8 + 2 * tg + 1];
            acc_o[j][0] *= cc0; acc_o[j][1] *= cc1;
            acc_o[j][2] *= cc0; acc_o[j][3] *= cc1;
        }
        #pragma unroll
        for (int kk = 0; kk < 64; kk += 8) {
            uint32_t a[4];
            // A = V^T, element (d, key) = Vs[key][d]
            a[0] = Vs[(kk + tg    ) * 68 + wrow + grp    ];
            a[1] = Vs[(kk + tg    ) * 68 + wrow + grp + 8];
            a[2] = Vs[(kk + tg + 4) * 68 + wrow + grp    ];
            a[3] = Vs[(kk + tg + 4) * 68 + wrow + grp + 8];
            #pragma unroll
            for (int j = 0; j < 8; j++) {
                uint32_t bf[2];
                // B = P^T col-major, element (key, qrow) = Ps[qrow][key]
                bf[0] = Ps[(j * 8 + grp) * 68 + kk + tg    ];
                bf[1] = Ps[(j * 8 + grp) * 68 + kk + tg + 4];
                mma_tf32(acc_o[j], a, bf);
            }
        }
    }

    // quad-reduce l and broadcast
    l0 += __shfl_xor_sync(0xffffffffu, l0, 1);
    l0 += __shfl_xor_sync(0xffffffffu, l0, 2);
    l1 += __shfl_xor_sync(0xffffffffu, l1, 1);
    l1 += __shfl_xor_sync(0xffffffffu, l1, 2);
    if (tg == 0) {
        sm_l[wrow + grp    ] = l0;
        sm_l[wrow + grp + 8] = l1;
    }
    __syncthreads();

    // write O: element (qrow=col, d=row) -> g_Y[(b,qt*64+col)][h*64+d]
    float* Yb = &g_Y[((size_t)(b * TT + qt * 64)) * CC + h * DD];
    #pragma unroll
    for (int j = 0; j < 8; j++) {
        int q0 = j * 8 + 2 * tg, q1 = q0 + 1;
        float i0 = 1.f / sm_l[q0];
        float i1 = 1.f / sm_l[q1];
        int d0 = wrow + grp, d1 = d0 + 8;
        Yb[q0 * CC + d0] = acc_o[j][0] * i0;
        Yb[q1 * CC + d0] = acc_o[j][1] * i1;
        Yb[q0 * CC + d1] = acc_o[j][2] * i0;
        Yb[q1 * CC + d1] = acc_o[j][3] * i1;
    }
}

// ---------------------------------------------------------------------------
extern "C" void kernel_launch(void* const* d_in, const int* in_sizes, int n_in,
                              void* d_out, int out_size)
{
    const float* x  = (const float*)d_in[0];
    const float* Wq = (const float*)d_in[1];
    const float* Wk = (const float*)d_in[2];
    const float* Wv = (const float*)d_in[3];
    const float* Wo = (const float*)d_in[4];
    float* out = (float*)d_out;

    const int smem_gemm = 51200;
    const int smem_attn = 4 * 64 * 68 * 4 + 2 * 64 * 4;   // 70144
    static bool attr_done = false;
    if (!attr_done) {
        cudaFuncSetAttribute(gemm_tf32_kernel<0>,
                             cudaFuncAttributeMaxDynamicSharedMemorySize, smem_gemm);
        cudaFuncSetAttribute(gemm_tf32_kernel<1>,
                             cudaFuncAttributeMaxDynamicSharedMemorySize, smem_gemm);
        cudaFuncSetAttribute(attn_mma_kernel,
                             cudaFuncAttributeMaxDynamicSharedMemorySize, smem_attn);
        attr_done = true;
    }

    dim3 g1(MTOT / 128, 512 / 128);
    gemm_tf32_kernel<0><<<g1, 256, smem_gemm>>>(x, Wq, Wk, Wv, nullptr);

    dim3 g2(TT / 64, HH, NB);
    attn_mma_kernel<<<g2, 128, smem_attn>>>();

    dim3 g3(MTOT / 128, CC / 128);
    gemm_tf32_kernel<1><<<g3, 256, smem_gemm>>>(nullptr, Wo, nullptr, nullptr, out);
}

// round 8
// speedup vs baseline: 3.6405x; 1.1183x over previous
#include <cuda_runtime.h>
#include <math.h>
#include <stdint.h>

#define NB 128
#define TT 384
#define CC 256
#define HH 4
#define KVH 2
#define DD 64
#define MTOT (NB*TT)   // 49152

// Scratch (static device globals — no allocations)
__device__ float g_Q[NB*HH*TT*DD];    // [B,H,T,D]
__device__ float g_K[NB*KVH*TT*DD];   // [B,KV,T,D]
__device__ float g_V[NB*KVH*TT*DD];   // [B,KV,T,D]
__device__ float g_Y[NB*TT*CC];       // [B*T, C] attention output

// ---------------------------------------------------------------------------
// tf32 helpers
// ---------------------------------------------------------------------------
__device__ __forceinline__ uint32_t f2tf32(float x) {
    uint32_t u;
    asm("cvt.rna.tf32.f32 %0, %1;" : "=r"(u) : "f"(x));
    return u;
}

__device__ __forceinline__ void mma_tf32(float* d, const uint32_t* a, const uint32_t* b) {
    asm volatile(
        "mma.sync.aligned.m16n8k8.row.col.f32.tf32.tf32.f32 "
        "{%0,%1,%2,%3}, {%4,%5,%6,%7}, {%8,%9}, {%0,%1,%2,%3};"
        : "+f"(d[0]), "+f"(d[1]), "+f"(d[2]), "+f"(d[3])
        : "r"(a[0]), "r"(a[1]), "r"(a[2]), "r"(a[3]),
          "r"(b[0]), "r"(b[1]));
}

__device__ __forceinline__ void cp16(uint32_t smem_addr, const float* g) {
    asm volatile("cp.async.cg.shared.global [%0], [%1], 16;\n"
                 :: "r"(smem_addr), "l"(g));
}

// ---------------------------------------------------------------------------
// tf32 GEMM, block tile 128x128, K=256 in 16-wide steps, 3-stage cp.async
// pipeline. 8 warps, each warp 64(M)x32(N) = 4x4 grid of m16n8k8 mmas.
// smem per stage: A raw fp32 [128][20] (2560 u32) + B raw fp32 [16][136]
// (2176 u32) = 4736 u32 = 18944 B; 3 stages = 56832 B. Epilogue Cs aliases.
// MODE 0: qkv projection + RoPE epilogue;  MODE 1: A = g_Y, B = Wo -> out
// ---------------------------------------------------------------------------
#define STG 4736
#define NK  16

template<int MODE>
__global__ __launch_bounds__(256, 2) void gemm_tf32_kernel(
    const float* __restrict__ Ain,
    const float* __restrict__ W0, const float* __restrict__ W1,
    const float* __restrict__ W2,
    float* __restrict__ out)
{
    extern __shared__ char smraw[];
    float* smf = (float*)smraw;
    const uint32_t smem_u32 = (uint32_t)__cvta_generic_to_shared(smraw);

    const float* A = (MODE == 1) ? (const float*)g_Y : Ain;

    const int m0 = blockIdx.x * 128;
    const int n0 = blockIdx.y * 128;

    const float* W; int ldb, noff;
    if (MODE == 1)     { W = W0; ldb = CC;  noff = n0;       }
    else if (n0 < 256) { W = W0; ldb = 256; noff = n0;       }
    else if (n0 < 384) { W = W1; ldb = 128; noff = n0 - 256; }
    else               { W = W2; ldb = 128; noff = n0 - 384; }

    const int tid  = threadIdx.x;
    const int lane = tid & 31;
    const int wid  = tid >> 5;
    const int wm   = wid >> 2;
    const int wn   = wid & 3;
    const int grp  = lane >> 2;
    const int tg   = lane & 3;

    // per-thread cp.async coordinates (constant across tiles)
    const int a_row0 = tid >> 2;              // + u*64
    const int a_seg  = (tid & 3) << 2;
    const int b_row0 = tid >> 5;              // + u*8
    const int b_off  = (tid & 31) << 2;

    float acc[4][4][4];
    #pragma unroll
    for (int i = 0; i < 4; i++)
        #pragma unroll
        for (int j = 0; j < 4; j++)
            #pragma unroll
            for (int r = 0; r < 4; r++) acc[i][j][r] = 0.f;

    // ---- issue helper (tile = k-index kt, stage s) ----
    auto issue = [&](int kt, int s) {
        const int k0 = kt * 16;
        const uint32_t sA = smem_u32 + s * STG * 4;
        const uint32_t sB = sA + 2560 * 4;
        #pragma unroll
        for (int u = 0; u < 2; u++) {
            int row = a_row0 + u * 64;
            cp16(sA + (row * 20 + a_seg) * 4, &A[(m0 + row) * CC + k0 + a_seg]);
        }
        #pragma unroll
        for (int u = 0; u < 2; u++) {
            int row = b_row0 + u * 8;
            cp16(sB + (row * 136 + b_off) * 4, &W[(k0 + row) * ldb + noff + b_off]);
        }
        asm volatile("cp.async.commit_group;\n" ::);
    };

    issue(0, 0);
    issue(1, 1);

    for (int kt = 0; kt < NK; kt++) {
        if (kt < NK - 1) asm volatile("cp.async.wait_group 1;\n" ::);
        else             asm volatile("cp.async.wait_group 0;\n" ::);
        __syncthreads();

        if (kt + 2 < NK) issue(kt + 2, (kt + 2) % 3);

        const float* Af = smf + (kt % 3) * STG;
        const float* Bf = Af + 2560;

        #pragma unroll
        for (int kk = 0; kk < 16; kk += 8) {
            uint32_t af[4][4];
            #pragma unroll
            for (int i = 0; i < 4; i++) {
                int mb = wm * 64 + i * 16 + grp;
                af[i][0] = f2tf32(Af[(mb    ) * 20 + kk + tg    ]);
                af[i][1] = f2tf32(Af[(mb + 8) * 20 + kk + tg    ]);
                af[i][2] = f2tf32(Af[(mb    ) * 20 + kk + tg + 4]);
                af[i][3] = f2tf32(Af[(mb + 8) * 20 + kk + tg + 4]);
            }
            uint32_t bf[4][2];
            #pragma unroll
            for (int j = 0; j < 4; j++) {
                int nb = wn * 32 + j * 8 + grp;
                bf[j][0] = f2tf32(Bf[(kk + tg    ) * 136 + nb]);
                bf[j][1] = f2tf32(Bf[(kk + tg + 4) * 136 + nb]);
            }
            #pragma unroll
            for (int i = 0; i < 4; i++)
                #pragma unroll
                for (int j = 0; j < 4; j++)
                    mma_tf32(acc[i][j], af[i], bf[j]);
        }
    }
    __syncthreads();   // mainloop reads done before Cs aliases stage memory

    float* Cs = smf;   // [64][132]

    #pragma unroll
    for (int half = 0; half < 2; half++) {
        if (wm == half) {
            #pragma unroll
            for (int i = 0; i < 4; i++)
                #pragma unroll
                for (int j = 0; j < 4; j++)
                    #pragma unroll
                    for (int rr = 0; rr < 4; rr++) {
                        int row = i * 16 + grp + ((rr >> 1) << 3);
                        int col = wn * 32 + j * 8 + tg * 2 + (rr & 1);
                        Cs[row * 132 + col] = acc[i][j][rr];
                    }
        }
        __syncthreads();

        const int r   = tid >> 2;
        const int seg = (tid & 3) << 5;
        const int gm  = m0 + half * 64 + r;
        const float* Crow = &Cs[r * 132];

        if (MODE == 1) {
            float* dst = &out[gm * CC + n0 + seg];
            #pragma unroll
            for (int c = 0; c < 32; c += 4)
                *reinterpret_cast<float4*>(&dst[c]) =
                    *reinterpret_cast<const float4*>(&Crow[seg + c]);
        } else {
            const int bb = gm / TT;
            const int t  = gm - bb * TT;
            const int cglob = n0 + seg;
            if (cglob >= 384) {
                int hh = (cglob - 384) >> 6;
                float* dst = &g_V[((bb * KVH + hh) * TT + t) * DD + (cglob & 63)];
                #pragma unroll
                for (int c = 0; c < 32; c += 4)
                    *reinterpret_cast<float4*>(&dst[c]) =
                        *reinterpret_cast<const float4*>(&Crow[seg + c]);
            } else {
                float* dst;
                if (cglob < 256) dst = &g_Q[((bb * HH  + (cglob >> 6)       ) * TT + t) * DD];
                else             dst = &g_K[((bb * KVH + ((cglob - 256) >> 6)) * TT + t) * DD];
                const int dhalf = cglob & 32;
                const float tf = (float)t;
                #pragma unroll
                for (int c = 0; c < 32; c += 4) {
                    float4 v;
                    float* vp = &v.x;
                    #pragma unroll
                    for (int e = 0; e < 4; e++) {
                        int cc = c + e;
                        float invf = exp2f(-0.41524101186f * (float)cc);
                        float ang = tf * invf;
                        float sn, cs;
                        sincosf(ang, &sn, &cs);
                        float val;
                        if (dhalf == 0)
                            val = Crow[seg + cc] * cs - Crow[seg + 32 + cc] * sn;
                        else
                            val = Crow[seg + cc] * cs + Crow[seg - 32 + cc] * sn;
                        vp[e] = val;
                    }
                    *reinterpret_cast<float4*>(&dst[dhalf + c]) = v;
                }
            }
        }
        __syncthreads();
    }
}

// ---------------------------------------------------------------------------
// Kernel 2: causal flash attention with tf32 mma. (unchanged from R5)
// ---------------------------------------------------------------------------
__global__ __launch_bounds__(128) void attn_mma_kernel()
{
    extern __shared__ uint32_t sm[];
    uint32_t* Qs = sm;
    uint32_t* Ks = Qs + 64 * 68;
    uint32_t* Vs = Ks + 64 * 68;
    uint32_t* Ps = Vs + 64 * 68;
    float* sm_corr = (float*)(Ps + 64 * 68);
    float* sm_l    = sm_corr + 64;

    const int qt = gridDim.x - 1 - blockIdx.x;
    const int h  = blockIdx.y;
    const int b  = blockIdx.z;
    const int kv = h >> 1;
    const int tid  = threadIdx.x;
    const int lane = tid & 31;
    const int wid  = tid >> 5;
    const int grp  = lane >> 2;
    const int tg   = lane & 3;
    const int wrow = wid * 16;

    const float* Qg = &g_Q[((b * HH + h) * TT + qt * 64) * DD];
    #pragma unroll
    for (int i = tid; i < 64 * 16; i += 128) {
        int r = i >> 4, c4 = (i & 15) << 2;
        float4 v = *reinterpret_cast<const float4*>(&Qg[r * 64 + c4]);
        uint4 u;
        u.x = f2tf32(v.x); u.y = f2tf32(v.y);
        u.z = f2tf32(v.z); u.w = f2tf32(v.w);
        *reinterpret_cast<uint4*>(&Qs[r * 68 + c4]) = u;
    }

    float m0 = -1e30f, m1 = -1e30f;
    float l0 = 0.f,   l1 = 0.f;
    float acc_o[8][4];
    #pragma unroll
    for (int j = 0; j < 8; j++)
        #pragma unroll
        for (int e = 0; e < 4; e++) acc_o[j][e] = 0.f;

    const float* Kg = &g_K[((b * KVH + kv) * TT) * DD];
    const float* Vg = &g_V[((b * KVH + kv) * TT) * DD];

    for (int kt = 0; kt <= qt; kt++) {
        __syncthreads();
        #pragma unroll
        for (int i = tid; i < 64 * 16; i += 128) {
            int r = i >> 4, c4 = (i & 15) << 2;
            float4 v = *reinterpret_cast<const float4*>(&Kg[(kt * 64 + r) * 64 + c4]);
            uint4 u;
            u.x = f2tf32(v.x); u.y = f2tf32(v.y);
            u.z = f2tf32(v.z); u.w = f2tf32(v.w);
            *reinterpret_cast<uint4*>(&Ks[r * 68 + c4]) = u;
            float4 w = *reinterpret_cast<const float4*>(&Vg[(kt * 64 + r) * 64 + c4]);
            uint4 uw;
            uw.x = f2tf32(w.x); uw.y = f2tf32(w.y);
            uw.z = f2tf32(w.z); uw.w = f2tf32(w.w);
            *reinterpret_cast<uint4*>(&Vs[r * 68 + c4]) = uw;
        }
        __syncthreads();

        float s[8][4];
        #pragma unroll
        for (int j = 0; j < 8; j++)
            #pragma unroll
            for (int e = 0; e < 4; e++) s[j][e] = 0.f;

        #pragma unroll
        for (int kk = 0; kk < 64; kk += 8) {
            uint32_t a[4];
            a[0] = Qs[(wrow + grp    ) * 68 + kk + tg    ];
            a[1] = Qs[(wrow + grp + 8) * 68 + kk + tg    ];
            a[2] = Qs[(wrow + grp    ) * 68 + kk + tg + 4];
            a[3] = Qs[(wrow + grp + 8) * 68 + kk + tg + 4];
            #pragma unroll
            for (int j = 0; j < 8; j++) {
                uint32_t bf[2];
                bf[0] = Ks[(j * 8 + grp) * 68 + kk + tg    ];
                bf[1] = Ks[(j * 8 + grp) * 68 + kk + tg + 4];
                mma_tf32(s[j], a, bf);
            }
        }

        const int row0 = qt * 64 + wrow + grp;
        const int row1 = row0 + 8;
        float mx0 = -1e30f, mx1 = -1e30f;
        #pragma unroll
        for (int j = 0; j < 8; j++) {
            #pragma unroll
            for (int e = 0; e < 4; e++) {
                float v = s[j][e] * 0.125f;
                if (kt == qt) {
                    int col = kt * 64 + j * 8 + 2 * tg + (e & 1);
                    int row = (e < 2) ? row0 : row1;
                    if (col > row) v = -1e30f;
                }
                s[j][e] = v;
            }
            mx0 = fmaxf(mx0, fmaxf(s[j][0], s[j][1]));
            mx1 = fmaxf(mx1, fmaxf(s[j][2], s[j][3]));
        }
        mx0 = fmaxf(mx0, __shfl_xor_sync(0xffffffffu, mx0, 1));
        mx0 = fmaxf(mx0, __shfl_xor_sync(0xffffffffu, mx0, 2));
        mx1 = fmaxf(mx1, __shfl_xor_sync(0xffffffffu, mx1, 1));
        mx1 = fmaxf(mx1, __shfl_xor_sync(0xffffffffu, mx1, 2));

        float mn0 = fmaxf(m0, mx0), mn1 = fmaxf(m1, mx1);
        float c0 = __expf(m0 - mn0), c1 = __expf(m1 - mn1);
        m0 = mn0; m1 = mn1;
        l0 *= c0; l1 *= c1;

        #pragma unroll
        for (int j = 0; j < 8; j++) {
            uint32_t p0 = f2tf32(__expf(s[j][0] - mn0));
            uint32_t p1 = f2tf32(__expf(s[j][1] - mn0));
            uint32_t p2 = f2tf32(__expf(s[j][2] - mn1));
            uint32_t p3 = f2tf32(__expf(s[j][3] - mn1));
            l0 += __uint_as_float(p0) + __uint_as_float(p1);
            l1 += __uint_as_float(p2) + __uint_as_float(p3);
            Ps[(wrow + grp    ) * 68 + j * 8 + 2 * tg    ] = p0;
            Ps[(wrow + grp    ) * 68 + j * 8 + 2 * tg + 1] = p1;
            Ps[(wrow + grp + 8) * 68 + j * 8 + 2 * tg    ] = p2;
            Ps[(wrow + grp + 8) * 68 + j * 8 + 2 * tg + 1] = p3;
        }
        if (tg == 0) {
            sm_corr[wrow + grp    ] = c0;
            sm_corr[wrow + grp + 8] = c1;
        }
        __syncthreads();

        #pragma unroll
        for (int j = 0; j < 8; j++) {
            float cc0 = sm_corr[j * 8 + 2 * tg    ];
            float cc1 = sm_corr[j * 8 + 2 * tg + 1];
            acc_o[j][0] *= cc0; acc_o[j][1] *= cc1;
            acc_o[j][2] *= cc0; acc_o[j][3] *= cc1;
        }
        #pragma unroll
        for (int kk = 0; kk < 64; kk += 8) {
            uint32_t a[4];
            a[0] = Vs[(kk + tg    ) * 68 + wrow + grp    ];
            a[1] = Vs[(kk + tg    ) * 68 + wrow + grp + 8];
            a[2] = Vs[(kk + tg + 4) * 68 + wrow + grp    ];
            a[3] = Vs[(kk + tg + 4) * 68 + wrow + grp + 8];
            #pragma unroll
            for (int j = 0; j < 8; j++) {
                uint32_t bf[2];
                bf[0] = Ps[(j * 8 + grp) * 68 + kk + tg    ];
                bf[1] = Ps[(j * 8 + grp) * 68 + kk + tg + 4];
                mma_tf32(acc_o[j], a, bf);
            }
        }
    }

    l0 += __shfl_xor_sync(0xffffffffu, l0, 1);
    l0 += __shfl_xor_sync(0xffffffffu, l0, 2);
    l1 += __shfl_xor_sync(0xffffffffu, l1, 1);
    l1 += __shfl_xor_sync(0xffffffffu, l1, 2);
    if (tg == 0) {
        sm_l[wrow + grp    ] = l0;
        sm_l[wrow + grp + 8] = l1;
    }
    __syncthreads();

    float* Yb = &g_Y[((size_t)(b * TT + qt * 64)) * CC + h * DD];
    #pragma unroll
    for (int j = 0; j < 8; j++) {
        int q0 = j * 8 + 2 * tg, q1 = q0 + 1;
        float i0 = 1.f / sm_l[q0];
        float i1 = 1.f / sm_l[q1];
        int d0 = wrow + grp, d1 = d0 + 8;
        Yb[q0 * CC + d0] = acc_o[j][0] * i0;
        Yb[q1 * CC + d0] = acc_o[j][1] * i1;
        Yb[q0 * CC + d1] = acc_o[j][2] * i0;
        Yb[q1 * CC + d1] = acc_o[j][3] * i1;
    }
}

// ---------------------------------------------------------------------------
extern "C" void kernel_launch(void* const* d_in, const int* in_sizes, int n_in,
                              void* d_out, int out_size)
{
    const float* x  = (const float*)d_in[0];
    const float* Wq = (const float*)d_in[1];
    const float* Wk = (const float*)d_in[2];
    const float* Wv = (const float*)d_in[3];
    const float* Wo = (const float*)d_in[4];
    float* out = (float*)d_out;

    const int smem_gemm = 3 * STG * 4;                      // 56832
    const int smem_attn = 4 * 64 * 68 * 4 + 2 * 64 * 4;     // 70144
    static bool attr_done = false;
    if (!attr_done) {
        cudaFuncSetAttribute(gemm_tf32_kernel<0>,
                             cudaFuncAttributeMaxDynamicSharedMemorySize, smem_gemm);
        cudaFuncSetAttribute(gemm_tf32_kernel<1>,
                             cudaFuncAttributeMaxDynamicSharedMemorySize, smem_gemm);
        cudaFuncSetAttribute(attn_mma_kernel,
                             cudaFuncAttributeMaxDynamicSharedMemorySize, smem_attn);
        attr_done = true;
    }

    dim3 g1(MTOT / 128, 512 / 128);
    gemm_tf32_kernel<0><<<g1, 256, smem_gemm>>>(x, Wq, Wk, Wv, nullptr);

    dim3 g2(TT / 64, HH, NB);
    attn_mma_kernel<<<g2, 128, smem_attn>>>();

    dim3 g3(MTOT / 128, CC / 128);
    gemm_tf32_kernel<1><<<g3, 256, smem_gemm>>>(nullptr, Wo, nullptr, nullptr, out);
}